// round 16
// baseline (speedup 1.0000x reference)
#include <cuda_runtime.h>
#include <cuda_bf16.h>
#include <math.h>
#include <stdint.h>

// Problem constants
#define B_    256
#define IC    1152
#define NU_   10
#define US    16
#define IU    8
#define NUU   160       // NU_*US
#define KTOT  9216      // IU*IC
#define KSPLIT 36
#define SA    72        // smem row stride (bf16): 144B -> bank stride 4 mod 32

// ---------------- device scratch ----------------
__device__ __align__(128) __nv_bfloat16 g_xh [B_ * KTOT];
__device__ __align__(128) __nv_bfloat16 g_xl [B_ * KTOT];
__device__ __align__(128) __nv_bfloat16 g_xth[KTOT * B_];
__device__ __align__(128) __nv_bfloat16 g_xtl[KTOT * B_];
__device__ __align__(128) float g_Wnk[NUU * KTOT];
__device__ __align__(128) float g_Wkn[KTOT * NUU];
__device__ __align__(128) __nv_bfloat16 g_SWth[NUU * KTOT];
__device__ __align__(128) __nv_bfloat16 g_SWtl[NUU * KTOT];
__device__ __align__(128) __nv_bfloat16 g_Vth[NUU * B_];
__device__ __align__(128) __nv_bfloat16 g_Vtl[NUU * B_];
__device__ __align__(128) float g_Spart[KSPLIT * B_ * NUU];   // 5.9 MB
__device__ __align__(128) float g_bp[IC * NU_ * 16];          // [j][n][p], p=i*2+bsplit
__device__ float g_logitsA[IC * NU_];
__device__ float g_logitsB[IC * NU_];

// ---------------- asm helpers ----------------
__device__ __forceinline__ uint32_t smem_to_u32(const void* p) {
    uint32_t a;
    asm("{ .reg .u64 t; cvta.to.shared.u64 t, %1; cvt.u32.u64 %0, t; }" : "=r"(a) : "l"(p));
    return a;
}
__device__ __forceinline__ void cpasync(uint32_t d, const void* g) {
    asm volatile("cp.async.cg.shared.global [%0], [%1], 16;" :: "r"(d), "l"(g));
}
#define CP_COMMIT() asm volatile("cp.async.commit_group;" ::: "memory")
#define CP_WAIT(n)  asm volatile("cp.async.wait_group %0;" :: "n"(n) : "memory")

__device__ __forceinline__ void ldsm_x4(uint32_t* r, uint32_t addr) {
    asm volatile("ldmatrix.sync.aligned.m8n8.x4.shared.b16 {%0,%1,%2,%3}, [%4];"
                 : "=r"(r[0]), "=r"(r[1]), "=r"(r[2]), "=r"(r[3]) : "r"(addr));
}
__device__ __forceinline__ void mma4(float* c, const uint32_t* a, uint32_t b0, uint32_t b1) {
    asm volatile("mma.sync.aligned.m16n8k16.row.col.f32.bf16.bf16.f32 "
        "{%0,%1,%2,%3}, {%4,%5,%6,%7}, {%8,%9}, {%0,%1,%2,%3};"
        : "+f"(c[0]), "+f"(c[1]), "+f"(c[2]), "+f"(c[3])
        : "r"(a[0]), "r"(a[1]), "r"(a[2]), "r"(a[3]), "r"(b0), "r"(b1));
}

// One 64-col K-chunk, 3-pass bf16-split, 10 n-frags per warp (R11-proven).
__device__ __forceinline__ void compute_chunk(uint32_t aH, uint32_t aL,
                                              uint32_t bH, uint32_t bL,
                                              int aRowByte, int bRowByte0,
                                              float acc[10][4]) {
#pragma unroll
    for (int kk = 0; kk < 4; kk++) {
        const int kb2 = kk * 32;
        uint32_t ah[4], al[4];
        ldsm_x4(ah, aH + aRowByte + kb2);
        ldsm_x4(al, aL + aRowByte + kb2);
#pragma unroll
        for (int fp = 0; fp < 5; fp++) {
            const int boff = bRowByte0 + fp * (16 * SA * 2) + kb2;
            uint32_t bh[4], bl[4];
            ldsm_x4(bh, bH + boff);
            ldsm_x4(bl, bL + boff);
            mma4(acc[2 * fp],     ah, bh[0], bh[2]);
            mma4(acc[2 * fp + 1], ah, bh[1], bh[3]);
            mma4(acc[2 * fp],     ah, bl[0], bl[2]);
            mma4(acc[2 * fp + 1], ah, bl[1], bl[3]);
            mma4(acc[2 * fp],     al, bh[0], bh[2]);
            mma4(acc[2 * fp + 1], al, bh[1], bh[3]);
        }
    }
}

// ---------------------------------------------------------------------------
// k_prex: split x -> bf16 hi/lo, row-major and transposed. grid (144,4)x256
// ---------------------------------------------------------------------------
__global__ void k_prex(const float* __restrict__ x) {
    __shared__ unsigned sh[64][65];
    const int k0 = blockIdx.x * 64, b0 = blockIdx.y * 64;
    const int tid = threadIdx.x;
#pragma unroll
    for (int i = 0; i < 16; i++) {
        int idx = tid + i * 256;
        int r = idx >> 6, c = idx & 63;
        size_t g = (size_t)(b0 + r) * KTOT + k0 + c;
        float v = x[g];
        __nv_bfloat16 h = __float2bfloat16_rn(v);
        __nv_bfloat16 l = __float2bfloat16_rn(v - __bfloat162float(h));
        g_xh[g] = h; g_xl[g] = l;
        sh[r][c] = ((unsigned)__bfloat16_as_ushort(l) << 16) | (unsigned)__bfloat16_as_ushort(h);
    }
    __syncthreads();
#pragma unroll
    for (int i = 0; i < 16; i++) {
        int idx = tid + i * 256;
        int rr = idx >> 6, cc = idx & 63;
        unsigned p = sh[cc][rr];
        size_t g = (size_t)(k0 + rr) * B_ + b0 + cc;
        g_xth[g] = __ushort_as_bfloat16((unsigned short)(p & 0xFFFF));
        g_xtl[g] = __ushort_as_bfloat16((unsigned short)(p >> 16));
    }
}

// ---------------------------------------------------------------------------
// k_pre_w: W[j,n,u,i] -> Wnk[nu][k], Wkn[k][nu], iter-0 scaled split; logitsA=0.
// grid 144x256
// ---------------------------------------------------------------------------
__global__ void k_pre_w(const float* __restrict__ W) {
    __shared__ float sm[8 * 1281];
    const int j0 = blockIdx.x * 8;
    const int tid = threadIdx.x;
#pragma unroll
    for (int i = 0; i < 40; i++) {
        int idx = tid + i * 256;
        int jl = idx / 1280, rem = idx - jl * 1280;
        sm[jl * 1281 + rem] = W[(size_t)(j0 + jl) * 1280 + rem];
    }
    __syncthreads();
#pragma unroll
    for (int t = 0; t < 40; t++) {
        int idx = tid + t * 256;                 // = nu*64 + ii*8 + jl
        int jl = idx & 7, ii = (idx >> 3) & 7, nu = idx >> 6;
        float v = sm[jl * 1281 + nu * 8 + ii];
        size_t gi = (size_t)nu * KTOT + ii * IC + j0 + jl;
        g_Wnk[gi] = v;
        float vs = v * (1.0f / (float)IC);       // iter-0 c is uniform
        __nv_bfloat16 h = __float2bfloat16_rn(vs);
        g_SWth[gi] = h;
        g_SWtl[gi] = __float2bfloat16_rn(vs - __bfloat162float(h));
    }
#pragma unroll
    for (int t = 0; t < 40; t++) {
        int idx = tid + t * 256;                 // = (ii*8 + jl)*160 + nu
        int nu = idx % 160, rest = idx / 160;
        int jl = rest & 7, ii = rest >> 3;
        g_Wkn[(size_t)(ii * IC + j0 + jl) * NUU + nu] = sm[jl * 1281 + nu * 8 + ii];
    }
    int gidx = blockIdx.x * 256 + tid;
    if (gidx < IC * NU_) g_logitsA[gidx] = 0.0f;
}

// ---------------------------------------------------------------------------
// k_softscale: fused b-update + softmax + W scale. grid 160 (block = nu), 256 thr.
//   lv[j] = lin[j,n] + (1/B) sum_p bp[j][n][p]   (ping-pong: lin/lout by parity)
//   block nu%16==0 writes lv to lout (race-free: no block reads lout this launch)
// ---------------------------------------------------------------------------
__global__ void __launch_bounds__(256) k_softscale(int parity) {
    const float* lin  = parity ? g_logitsB : g_logitsA;
    float*       lout = parity ? g_logitsA : g_logitsB;
    __shared__ float cs[IC];
    __shared__ float red[8];
    const int nu = blockIdx.x;
    const int n = nu >> 4;
    const int tid = threadIdx.x;

    float lv[5];
    float lmax = -1e30f;
#pragma unroll
    for (int i = 0; i < 5; i++) {
        int j = tid + i * 256;
        float v = -1e30f;
        if (j < IC) {
            const float4* bp4 = reinterpret_cast<const float4*>(
                g_bp + ((size_t)j * NU_ + n) * 16);
            float4 a0 = bp4[0], a1 = bp4[1], a2 = bp4[2], a3 = bp4[3];
            float s = (a0.x + a0.y + a0.z + a0.w) + (a1.x + a1.y + a1.z + a1.w)
                    + (a2.x + a2.y + a2.z + a2.w) + (a3.x + a3.y + a3.z + a3.w);
            v = lin[j * NU_ + n] + s * (1.0f / (float)B_);
            if ((nu & 15) == 0) lout[j * NU_ + n] = v;
        }
        lv[i] = v;
        lmax = fmaxf(lmax, v);
    }
#pragma unroll
    for (int off = 16; off; off >>= 1)
        lmax = fmaxf(lmax, __shfl_xor_sync(0xffffffffu, lmax, off));
    if ((tid & 31) == 0) red[tid >> 5] = lmax;
    __syncthreads();
    float bmax = fmaxf(fmaxf(fmaxf(red[0], red[1]), fmaxf(red[2], red[3])),
                       fmaxf(fmaxf(red[4], red[5]), fmaxf(red[6], red[7])));
    __syncthreads();
    float lsum = 0.0f;
#pragma unroll
    for (int i = 0; i < 5; i++) {
        int j = tid + i * 256;
        if (j < IC) {
            float e = expf(lv[i] - bmax);
            cs[j] = e;
            lsum += e;
        }
    }
#pragma unroll
    for (int off = 16; off; off >>= 1)
        lsum += __shfl_xor_sync(0xffffffffu, lsum, off);
    if ((tid & 31) == 0) red[tid >> 5] = lsum;
    __syncthreads();
    const float inv = 1.0f / (red[0] + red[1] + red[2] + red[3] +
                              red[4] + red[5] + red[6] + red[7]);

#pragma unroll
    for (int i = 0; i < 9; i++) {
        int e4 = tid + i * 256;
        int k = e4 * 4;
        int j = k % IC;
        float4 w = *reinterpret_cast<const float4*>(g_Wnk + (size_t)nu * KTOT + k);
        float v0 = w.x * cs[j] * inv,     v1 = w.y * cs[j + 1] * inv;
        float v2 = w.z * cs[j + 2] * inv, v3 = w.w * cs[j + 3] * inv;
        __nv_bfloat16 h0 = __float2bfloat16_rn(v0), h1 = __float2bfloat16_rn(v1);
        __nv_bfloat16 h2 = __float2bfloat16_rn(v2), h3 = __float2bfloat16_rn(v3);
        __nv_bfloat16 l0 = __float2bfloat16_rn(v0 - __bfloat162float(h0));
        __nv_bfloat16 l1 = __float2bfloat16_rn(v1 - __bfloat162float(h1));
        __nv_bfloat16 l2 = __float2bfloat16_rn(v2 - __bfloat162float(h2));
        __nv_bfloat16 l3 = __float2bfloat16_rn(v3 - __bfloat162float(h3));
        uint2 ph, pl;
        ph.x = ((unsigned)__bfloat16_as_ushort(h1) << 16) | __bfloat16_as_ushort(h0);
        ph.y = ((unsigned)__bfloat16_as_ushort(h3) << 16) | __bfloat16_as_ushort(h2);
        pl.x = ((unsigned)__bfloat16_as_ushort(l1) << 16) | __bfloat16_as_ushort(l0);
        pl.y = ((unsigned)__bfloat16_as_ushort(l3) << 16) | __bfloat16_as_ushort(l2);
        *reinterpret_cast<uint2*>(g_SWth + (size_t)nu * KTOT + k) = ph;
        *reinterpret_cast<uint2*>(g_SWtl + (size_t)nu * KTOT + k) = pl;
    }
}

// ---------------------------------------------------------------------------
// GEMM1: Spart[ks][b-tile 64][nu] = X * (c.W)^T over 256-k chunk. grid 144x256.
// 3-stage pipeline (R11-proven, untouched).
// ---------------------------------------------------------------------------
#define BUF1 (448 * SA * 2)          // 64512 B
#define G1_SMEM (3 * BUF1)           // 193536

__device__ __forceinline__ void g1_load(uint32_t sb, int m0, int col, int tid) {
#pragma unroll
    for (int t = 0; t < 2; t++) {
        int idx = tid + t * 256;
        int r = idx >> 3, q = idx & 7;
        uint32_t d = sb + (uint32_t)(r * SA + q * 8) * 2;
        size_t g = (size_t)(m0 + r) * KTOT + col + q * 8;
        cpasync(d, g_xh + g);
        cpasync(d + 64 * SA * 2, g_xl + g);
    }
#pragma unroll
    for (int t = 0; t < 5; t++) {
        int idx = tid + t * 256;
        int r = idx >> 3, q = idx & 7;
        uint32_t d = sb + 128 * SA * 2 + (uint32_t)(r * SA + q * 8) * 2;
        size_t g = (size_t)r * KTOT + col + q * 8;
        cpasync(d, g_SWth + g);
        cpasync(d + 160 * SA * 2, g_SWtl + g);
    }
}

__global__ void __launch_bounds__(256) k_hmma1() {
    extern __shared__ char sm[];
    const int mt = blockIdx.x & 3, ks = blockIdx.x >> 2;
    const int m0 = mt * 64, kbase = ks * 256;
    const int tid = threadIdx.x, warp = tid >> 5, lane = tid & 31;
    const int wm = warp & 3, wn = warp >> 2;
    const int lg = lane >> 2, lt = lane & 3;
    const uint32_t sb = smem_to_u32(sm);

    const int aRowByte = ((wm * 16 + (lane & 15)) * SA + (lane >> 4) * 8) * 2;
    const int bRowByte0 = ((wn * 80 + (lane & 15)) * SA + (lane >> 4) * 8) * 2;

    float acc[10][4];
#pragma unroll
    for (int f = 0; f < 10; f++)
#pragma unroll
        for (int q = 0; q < 4; q++) acc[f][q] = 0.0f;

#define G1_BUFS(base) (base), (base) + 64 * SA * 2, (base) + 128 * SA * 2, (base) + 288 * SA * 2

    g1_load(sb,            m0, kbase,       tid); CP_COMMIT();
    g1_load(sb + BUF1,     m0, kbase + 64,  tid); CP_COMMIT();
    g1_load(sb + 2 * BUF1, m0, kbase + 128, tid); CP_COMMIT();

    CP_WAIT(2); __syncthreads();
    compute_chunk(G1_BUFS(sb), aRowByte, bRowByte0, acc);
    __syncthreads();
    g1_load(sb, m0, kbase + 192, tid); CP_COMMIT();

    CP_WAIT(2); __syncthreads();
    compute_chunk(G1_BUFS(sb + BUF1), aRowByte, bRowByte0, acc);

    CP_WAIT(1); __syncthreads();
    compute_chunk(G1_BUFS(sb + 2 * BUF1), aRowByte, bRowByte0, acc);

    CP_WAIT(0); __syncthreads();
    compute_chunk(G1_BUFS(sb), aRowByte, bRowByte0, acc);

    float* base = g_Spart + (size_t)ks * (B_ * NUU);
    const int r0 = m0 + wm * 16 + lg;
#pragma unroll
    for (int f = 0; f < 10; f++) {
        const int nu = wn * 80 + f * 8 + lt * 2;
        *reinterpret_cast<float2*>(base + (size_t)r0 * NUU + nu)       = make_float2(acc[f][0], acc[f][1]);
        *reinterpret_cast<float2*>(base + (size_t)(r0 + 8) * NUU + nu) = make_float2(acc[f][2], acc[f][3]);
    }
}

// ---------------------------------------------------------------------------
// GEMM2 + fused b-update partials. SINGLE buffer (83KB) -> 2 CTAs/SM.
//   G[k,nu] = sum_{b in half} Xt[k][b] Vt[nu][b];
//   bp[j][n][i*2+bsplit] = sum_u Wkn[k][nu]*G[k][nu]   (k = i*IC + j)
// grid 144 (= kt 0..71 x bsplit), 512 threads.
// ---------------------------------------------------------------------------
#define BUF2 (576 * SA * 2)          // 82944 B
#define G2_SMEM BUF2                 // single buffer

__device__ __forceinline__ void g2_load(uint32_t sb, int k0, int col, int tid) {
#pragma unroll
    for (int t = 0; t < 2; t++) {
        int idx = tid + t * 512;
        int r = idx >> 3, q = idx & 7;
        uint32_t d = sb + (uint32_t)(r * SA + q * 8) * 2;
        size_t g = (size_t)(k0 + r) * B_ + col + q * 8;
        cpasync(d, g_xth + g);
        cpasync(d + 128 * SA * 2, g_xtl + g);
    }
#pragma unroll
    for (int t = 0; t < 3; t++) {
        int idx = tid + t * 512;
        if (idx < 1280) {
            int r = idx >> 3, q = idx & 7;
            uint32_t d = sb + 256 * SA * 2 + (uint32_t)(r * SA + q * 8) * 2;
            size_t g = (size_t)r * B_ + col + q * 8;
            cpasync(d, g_Vth + g);
            cpasync(d + 160 * SA * 2, g_Vtl + g);
        }
    }
}

__global__ void __launch_bounds__(512, 2) k_hmma2() {
    extern __shared__ char sm[];
    const int ksp = blockIdx.x & 1;
    const int k0 = (blockIdx.x >> 1) * 128;
    const int col0 = ksp * 128;
    const int tid = threadIdx.x, warp = tid >> 5, lane = tid & 31;
    const int wm = warp >> 1, wn = warp & 1;
    const int lg = lane >> 2, lt = lane & 3;
    const uint32_t sb = smem_to_u32(sm);

    const int aRowByte = ((wm * 16 + (lane & 15)) * SA + (lane >> 4) * 8) * 2;
    const int bRowByte0 = ((wn * 80 + (lane & 15)) * SA + (lane >> 4) * 8) * 2;

    float acc[10][4];
#pragma unroll
    for (int f = 0; f < 10; f++)
#pragma unroll
        for (int q = 0; q < 4; q++) acc[f][q] = 0.0f;

#define G2_BUFS(base) (base), (base) + 128 * SA * 2, (base) + 256 * SA * 2, (base) + 416 * SA * 2

    g2_load(sb, k0, col0, tid); CP_COMMIT();
    CP_WAIT(0); __syncthreads();
    compute_chunk(G2_BUFS(sb), aRowByte, bRowByte0, acc);
    __syncthreads();

    g2_load(sb, k0, col0 + 64, tid); CP_COMMIT();
    CP_WAIT(0); __syncthreads();
    compute_chunk(G2_BUFS(sb), aRowByte, bRowByte0, acc);

    // fused epilogue: contract with Wkn, quad-reduce over lt, emit bp partials.
    const int i_idx = k0 / IC;                 // 1152 = 9*128: tiles don't cross i
    const int j0 = k0 % IC;
    const int p = i_idx * 2 + ksp;
    const int rbase = wm * 16 + lg;
#pragma unroll
    for (int rh = 0; rh < 2; rh++) {
        const int row = rbase + rh * 8;
        const float* wrow = g_Wkn + (size_t)(k0 + row) * NUU;
#pragma unroll
        for (int q = 0; q < 5; q++) {
            const int f0 = 2 * q;
            const int nu0 = wn * 80 + f0 * 8 + lt * 2;
            float2 w0 = *reinterpret_cast<const float2*>(wrow + nu0);
            float2 w1 = *reinterpret_cast<const float2*>(wrow + nu0 + 8);
            float s = acc[f0][rh * 2] * w0.x + acc[f0][rh * 2 + 1] * w0.y
                    + acc[f0 + 1][rh * 2] * w1.x + acc[f0 + 1][rh * 2 + 1] * w1.y;
            s += __shfl_xor_sync(0xffffffffu, s, 1);
            s += __shfl_xor_sync(0xffffffffu, s, 2);
            if (lt == 0)
                g_bp[((size_t)(j0 + row) * NU_ + (wn * 5 + q)) * 16 + p] = s;
        }
    }
}

// ---------------------------------------------------------------------------
// k_squash: reduce 36 splits (12 groups x 3, float4 loads), squash.
// grid 256, 480 threads. (R11-proven)
// ---------------------------------------------------------------------------
__global__ void __launch_bounds__(480) k_squash(float* __restrict__ out, int final_iter) {
    const int b = blockIdx.x;
    const int tid = threadIdx.x;          // 0..479
    const int g = tid / 40, q4 = tid - (tid / 40) * 40;

    __shared__ float partial[12][NUU];
    __shared__ float sq[NUU];
    __shared__ float mag[US];

    float4 s4 = make_float4(0.f, 0.f, 0.f, 0.f);
#pragma unroll
    for (int m = 0; m < 3; m++) {
        const float4 v = *reinterpret_cast<const float4*>(
            g_Spart + (size_t)(g * 3 + m) * (B_ * NUU) + b * NUU + q4 * 4);
        s4.x += v.x; s4.y += v.y; s4.z += v.z; s4.w += v.w;
    }
    *reinterpret_cast<float4*>(&partial[g][q4 * 4]) = s4;
    __syncthreads();

    if (tid < NUU) {
        float s = 0.0f;
#pragma unroll
        for (int gg = 0; gg < 12; gg++) s += partial[gg][tid];
        sq[tid] = s * s;
        partial[0][tid] = s;
    }
    __syncthreads();
    if (tid < US) {
        float m = 0.0f;
#pragma unroll
        for (int n = 0; n < NU_; n++) m += sq[n * US + tid];
        mag[tid] = m;
    }
    __syncthreads();
    if (tid < NUU) {
        float s = partial[0][tid];
        float m = mag[tid & 15];
        float v = s * (m / ((1.0f + m) * sqrtf(m)));
        if (final_iter) {
            out[b * NUU + tid] = v;
        } else {
            __nv_bfloat16 h = __float2bfloat16_rn(v);
            __nv_bfloat16 l = __float2bfloat16_rn(v - __bfloat162float(h));
            g_Vth[tid * B_ + b] = h;
            g_Vtl[tid * B_ + b] = l;
        }
    }
}

// ---------------------------------------------------------------------------
extern "C" void kernel_launch(void* const* d_in, const int* in_sizes, int n_in,
                              void* d_out, int out_size) {
    const float* x = (const float*)d_in[0];   // [256, 8, 1152]
    const float* W = (const float*)d_in[1];   // [1152, 10, 16, 8]
    float* out = (float*)d_out;

    cudaFuncSetAttribute(k_hmma1, cudaFuncAttributeMaxDynamicSharedMemorySize, G1_SMEM);
    cudaFuncSetAttribute(k_hmma2, cudaFuncAttributeMaxDynamicSharedMemorySize, G2_SMEM);

    k_prex<<<dim3(KTOT / 64, B_ / 64), 256>>>(x);
    k_pre_w<<<IC / 8, 256>>>(W);              // also emits iter-0 scaled W split

    // iter 0: logitsA (zeros) -> logitsB
    k_hmma1<<<4 * KSPLIT, 256, G1_SMEM>>>();
    k_squash<<<B_, 480>>>(nullptr, 0);
    k_hmma2<<<144, 512, G2_SMEM>>>();
    k_softscale<<<NUU, 256>>>(0);
    // iter 1: logitsB -> logitsA
    k_hmma1<<<4 * KSPLIT, 256, G1_SMEM>>>();
    k_squash<<<B_, 480>>>(nullptr, 0);
    k_hmma2<<<144, 512, G2_SMEM>>>();
    k_softscale<<<NUU, 256>>>(1);
    // iter 2 (final)
    k_hmma1<<<4 * KSPLIT, 256, G1_SMEM>>>();
    k_squash<<<B_, 480>>>(out, 1);
}

// round 17
// speedup vs baseline: 1.1855x; 1.1855x over previous
#include <cuda_runtime.h>
#include <cuda_bf16.h>
#include <math.h>
#include <stdint.h>

// Problem constants
#define B_    256
#define IC    1152
#define NU_   10
#define US    16
#define IU    8
#define NUU   160       // NU_*US
#define KTOT  9216      // IU*IC
#define KSPLIT 36
#define SA    72        // smem row stride (bf16): 144B -> bank stride 4 mod 32

// ---------------- device scratch ----------------
__device__ __align__(128) __nv_bfloat16 g_xh [B_ * KTOT];
__device__ __align__(128) __nv_bfloat16 g_xl [B_ * KTOT];
__device__ __align__(128) __nv_bfloat16 g_xth[KTOT * B_];
__device__ __align__(128) __nv_bfloat16 g_xtl[KTOT * B_];
__device__ __align__(128) float g_Wnk[NUU * KTOT];
__device__ __align__(128) float g_Wkn[KTOT * NUU];
__device__ __align__(128) __nv_bfloat16 g_SWth[NUU * KTOT];
__device__ __align__(128) __nv_bfloat16 g_SWtl[NUU * KTOT];
__device__ __align__(128) __nv_bfloat16 g_Vth[NUU * B_];
__device__ __align__(128) __nv_bfloat16 g_Vtl[NUU * B_];
__device__ __align__(128) float g_Spart[KSPLIT * B_ * NUU];   // 5.9 MB
__device__ __align__(128) float g_bp[16 * IC * NU_];          // [i*2+bsplit][j][n]
__device__ float g_logits[IC * NU_];

// ---------------- asm helpers ----------------
__device__ __forceinline__ uint32_t smem_to_u32(const void* p) {
    uint32_t a;
    asm("{ .reg .u64 t; cvta.to.shared.u64 t, %1; cvt.u32.u64 %0, t; }" : "=r"(a) : "l"(p));
    return a;
}
__device__ __forceinline__ void cpasync(uint32_t d, const void* g) {
    asm volatile("cp.async.cg.shared.global [%0], [%1], 16;" :: "r"(d), "l"(g));
}
#define CP_COMMIT() asm volatile("cp.async.commit_group;" ::: "memory")
#define CP_WAIT(n)  asm volatile("cp.async.wait_group %0;" :: "n"(n) : "memory")

__device__ __forceinline__ void ldsm_x4(uint32_t* r, uint32_t addr) {
    asm volatile("ldmatrix.sync.aligned.m8n8.x4.shared.b16 {%0,%1,%2,%3}, [%4];"
                 : "=r"(r[0]), "=r"(r[1]), "=r"(r[2]), "=r"(r[3]) : "r"(addr));
}
__device__ __forceinline__ void mma4(float* c, const uint32_t* a, uint32_t b0, uint32_t b1) {
    asm volatile("mma.sync.aligned.m16n8k16.row.col.f32.bf16.bf16.f32 "
        "{%0,%1,%2,%3}, {%4,%5,%6,%7}, {%8,%9}, {%0,%1,%2,%3};"
        : "+f"(c[0]), "+f"(c[1]), "+f"(c[2]), "+f"(c[3])
        : "r"(a[0]), "r"(a[1]), "r"(a[2]), "r"(a[3]), "r"(b0), "r"(b1));
}

// One 64-col K-chunk, 3-pass bf16-split, 10 n-frags per warp (R11-proven).
__device__ __forceinline__ void compute_chunk(uint32_t aH, uint32_t aL,
                                              uint32_t bH, uint32_t bL,
                                              int aRowByte, int bRowByte0,
                                              float acc[10][4]) {
#pragma unroll
    for (int kk = 0; kk < 4; kk++) {
        const int kb2 = kk * 32;
        uint32_t ah[4], al[4];
        ldsm_x4(ah, aH + aRowByte + kb2);
        ldsm_x4(al, aL + aRowByte + kb2);
#pragma unroll
        for (int fp = 0; fp < 5; fp++) {
            const int boff = bRowByte0 + fp * (16 * SA * 2) + kb2;
            uint32_t bh[4], bl[4];
            ldsm_x4(bh, bH + boff);
            ldsm_x4(bl, bL + boff);
            mma4(acc[2 * fp],     ah, bh[0], bh[2]);
            mma4(acc[2 * fp + 1], ah, bh[1], bh[3]);
            mma4(acc[2 * fp],     ah, bl[0], bl[2]);
            mma4(acc[2 * fp + 1], ah, bl[1], bl[3]);
            mma4(acc[2 * fp],     al, bh[0], bh[2]);
            mma4(acc[2 * fp + 1], al, bh[1], bh[3]);
        }
    }
}

// ---------------------------------------------------------------------------
// k_prex: split x -> bf16 hi/lo, row-major and transposed. grid (144,4)x256.
// Vectorized: float4 loads, uint2 packed bf16 stores (4 elems/thread/iter).
// ---------------------------------------------------------------------------
__global__ void k_prex(const float* __restrict__ x) {
    __shared__ unsigned sh[64][65];
    const int k0 = blockIdx.x * 64, b0 = blockIdx.y * 64;
    const int tid = threadIdx.x;
#pragma unroll
    for (int i = 0; i < 4; i++) {
        int idx = tid + i * 256;                 // 0..1023
        int r = idx >> 4, c4 = idx & 15;         // r = b-local, c4 = k-quad
        size_t g = (size_t)(b0 + r) * KTOT + k0 + c4 * 4;
        float4 v = *reinterpret_cast<const float4*>(x + g);
        __nv_bfloat16 h0 = __float2bfloat16_rn(v.x), h1 = __float2bfloat16_rn(v.y);
        __nv_bfloat16 h2 = __float2bfloat16_rn(v.z), h3 = __float2bfloat16_rn(v.w);
        __nv_bfloat16 l0 = __float2bfloat16_rn(v.x - __bfloat162float(h0));
        __nv_bfloat16 l1 = __float2bfloat16_rn(v.y - __bfloat162float(h1));
        __nv_bfloat16 l2 = __float2bfloat16_rn(v.z - __bfloat162float(h2));
        __nv_bfloat16 l3 = __float2bfloat16_rn(v.w - __bfloat162float(h3));
        uint2 ph, pl;
        ph.x = ((unsigned)__bfloat16_as_ushort(h1) << 16) | __bfloat16_as_ushort(h0);
        ph.y = ((unsigned)__bfloat16_as_ushort(h3) << 16) | __bfloat16_as_ushort(h2);
        pl.x = ((unsigned)__bfloat16_as_ushort(l1) << 16) | __bfloat16_as_ushort(l0);
        pl.y = ((unsigned)__bfloat16_as_ushort(l3) << 16) | __bfloat16_as_ushort(l2);
        *reinterpret_cast<uint2*>(g_xh + g) = ph;
        *reinterpret_cast<uint2*>(g_xl + g) = pl;
        const int c = c4 * 4;
        sh[r][c]     = ((unsigned)__bfloat16_as_ushort(l0) << 16) | __bfloat16_as_ushort(h0);
        sh[r][c + 1] = ((unsigned)__bfloat16_as_ushort(l1) << 16) | __bfloat16_as_ushort(h1);
        sh[r][c + 2] = ((unsigned)__bfloat16_as_ushort(l2) << 16) | __bfloat16_as_ushort(h2);
        sh[r][c + 3] = ((unsigned)__bfloat16_as_ushort(l3) << 16) | __bfloat16_as_ushort(h3);
    }
    __syncthreads();
#pragma unroll
    for (int i = 0; i < 16; i++) {
        int idx = tid + i * 256;
        int rr = idx >> 6, cc = idx & 63;        // rr = k-local, cc = b-local
        unsigned p = sh[cc][rr];
        size_t g = (size_t)(k0 + rr) * B_ + b0 + cc;
        g_xth[g] = __ushort_as_bfloat16((unsigned short)(p & 0xFFFF));
        g_xtl[g] = __ushort_as_bfloat16((unsigned short)(p >> 16));
    }
}

// ---------------------------------------------------------------------------
// k_pre_w: W[j,n,u,i] -> Wnk[nu][k], Wkn[k][nu], iter-0 scaled split; logits=0.
// grid 144x256
// ---------------------------------------------------------------------------
__global__ void k_pre_w(const float* __restrict__ W) {
    __shared__ float sm[8 * 1281];
    const int j0 = blockIdx.x * 8;
    const int tid = threadIdx.x;
#pragma unroll
    for (int i = 0; i < 40; i++) {
        int idx = tid + i * 256;
        int jl = idx / 1280, rem = idx - jl * 1280;
        sm[jl * 1281 + rem] = W[(size_t)(j0 + jl) * 1280 + rem];
    }
    __syncthreads();
#pragma unroll
    for (int t = 0; t < 40; t++) {
        int idx = tid + t * 256;                 // = nu*64 + ii*8 + jl
        int jl = idx & 7, ii = (idx >> 3) & 7, nu = idx >> 6;
        float v = sm[jl * 1281 + nu * 8 + ii];
        size_t gi = (size_t)nu * KTOT + ii * IC + j0 + jl;
        g_Wnk[gi] = v;
        float vs = v * (1.0f / (float)IC);       // iter-0 c is uniform
        __nv_bfloat16 h = __float2bfloat16_rn(vs);
        g_SWth[gi] = h;
        g_SWtl[gi] = __float2bfloat16_rn(vs - __bfloat162float(h));
    }
#pragma unroll
    for (int t = 0; t < 40; t++) {
        int idx = tid + t * 256;                 // = (ii*8 + jl)*160 + nu
        int nu = idx % 160, rest = idx / 160;
        int jl = rest & 7, ii = rest >> 3;
        g_Wkn[(size_t)(ii * IC + j0 + jl) * NUU + nu] = sm[jl * 1281 + nu * 8 + ii];
    }
    int gidx = blockIdx.x * 256 + tid;
    if (gidx < IC * NU_) g_logits[gidx] = 0.0f;
}

// ---------------------------------------------------------------------------
// k_softscale: per-nu softmax over j (from logits) + W scale + bf16 split.
// grid 160 (block = nu), 256 threads. (R11-proven)
// ---------------------------------------------------------------------------
__global__ void __launch_bounds__(256) k_softscale() {
    __shared__ float cs[IC];
    __shared__ float red[8];
    const int nu = blockIdx.x;
    const int n = nu >> 4;
    const int tid = threadIdx.x;

    float lv[5];
    float lmax = -1e30f;
#pragma unroll
    for (int i = 0; i < 5; i++) {
        int j = tid + i * 256;
        lv[i] = (j < IC) ? g_logits[j * NU_ + n] : -1e30f;
        lmax = fmaxf(lmax, lv[i]);
    }
#pragma unroll
    for (int off = 16; off; off >>= 1)
        lmax = fmaxf(lmax, __shfl_xor_sync(0xffffffffu, lmax, off));
    if ((tid & 31) == 0) red[tid >> 5] = lmax;
    __syncthreads();
    float bmax = fmaxf(fmaxf(fmaxf(red[0], red[1]), fmaxf(red[2], red[3])),
                       fmaxf(fmaxf(red[4], red[5]), fmaxf(red[6], red[7])));
    __syncthreads();
    float lsum = 0.0f;
#pragma unroll
    for (int i = 0; i < 5; i++) {
        int j = tid + i * 256;
        if (j < IC) {
            float e = expf(lv[i] - bmax);
            cs[j] = e;
            lsum += e;
        }
    }
#pragma unroll
    for (int off = 16; off; off >>= 1)
        lsum += __shfl_xor_sync(0xffffffffu, lsum, off);
    if ((tid & 31) == 0) red[tid >> 5] = lsum;
    __syncthreads();
    const float inv = 1.0f / (red[0] + red[1] + red[2] + red[3] +
                              red[4] + red[5] + red[6] + red[7]);

#pragma unroll
    for (int i = 0; i < 9; i++) {
        int e4 = tid + i * 256;
        int k = e4 * 4;
        int j = k % IC;
        float4 w = *reinterpret_cast<const float4*>(g_Wnk + (size_t)nu * KTOT + k);
        float v0 = w.x * cs[j] * inv,     v1 = w.y * cs[j + 1] * inv;
        float v2 = w.z * cs[j + 2] * inv, v3 = w.w * cs[j + 3] * inv;
        __nv_bfloat16 h0 = __float2bfloat16_rn(v0), h1 = __float2bfloat16_rn(v1);
        __nv_bfloat16 h2 = __float2bfloat16_rn(v2), h3 = __float2bfloat16_rn(v3);
        __nv_bfloat16 l0 = __float2bfloat16_rn(v0 - __bfloat162float(h0));
        __nv_bfloat16 l1 = __float2bfloat16_rn(v1 - __bfloat162float(h1));
        __nv_bfloat16 l2 = __float2bfloat16_rn(v2 - __bfloat162float(h2));
        __nv_bfloat16 l3 = __float2bfloat16_rn(v3 - __bfloat162float(h3));
        uint2 ph, pl;
        ph.x = ((unsigned)__bfloat16_as_ushort(h1) << 16) | __bfloat16_as_ushort(h0);
        ph.y = ((unsigned)__bfloat16_as_ushort(h3) << 16) | __bfloat16_as_ushort(h2);
        pl.x = ((unsigned)__bfloat16_as_ushort(l1) << 16) | __bfloat16_as_ushort(l0);
        pl.y = ((unsigned)__bfloat16_as_ushort(l3) << 16) | __bfloat16_as_ushort(l2);
        *reinterpret_cast<uint2*>(g_SWth + (size_t)nu * KTOT + k) = ph;
        *reinterpret_cast<uint2*>(g_SWtl + (size_t)nu * KTOT + k) = pl;
    }
}

// ---------------------------------------------------------------------------
// GEMM1: Spart[ks][b-tile 64][nu] = X * (c.W)^T over 256-k chunk. grid 144x256.
// 3-stage pipeline (R11-proven, untouched).
// ---------------------------------------------------------------------------
#define BUF1 (448 * SA * 2)          // 64512 B
#define G1_SMEM (3 * BUF1)           // 193536

__device__ __forceinline__ void g1_load(uint32_t sb, int m0, int col, int tid) {
#pragma unroll
    for (int t = 0; t < 2; t++) {
        int idx = tid + t * 256;
        int r = idx >> 3, q = idx & 7;
        uint32_t d = sb + (uint32_t)(r * SA + q * 8) * 2;
        size_t g = (size_t)(m0 + r) * KTOT + col + q * 8;
        cpasync(d, g_xh + g);
        cpasync(d + 64 * SA * 2, g_xl + g);
    }
#pragma unroll
    for (int t = 0; t < 5; t++) {
        int idx = tid + t * 256;
        int r = idx >> 3, q = idx & 7;
        uint32_t d = sb + 128 * SA * 2 + (uint32_t)(r * SA + q * 8) * 2;
        size_t g = (size_t)r * KTOT + col + q * 8;
        cpasync(d, g_SWth + g);
        cpasync(d + 160 * SA * 2, g_SWtl + g);
    }
}

__global__ void __launch_bounds__(256) k_hmma1() {
    extern __shared__ char sm[];
    const int mt = blockIdx.x & 3, ks = blockIdx.x >> 2;
    const int m0 = mt * 64, kbase = ks * 256;
    const int tid = threadIdx.x, warp = tid >> 5, lane = tid & 31;
    const int wm = warp & 3, wn = warp >> 2;
    const int lg = lane >> 2, lt = lane & 3;
    const uint32_t sb = smem_to_u32(sm);

    const int aRowByte = ((wm * 16 + (lane & 15)) * SA + (lane >> 4) * 8) * 2;
    const int bRowByte0 = ((wn * 80 + (lane & 15)) * SA + (lane >> 4) * 8) * 2;

    float acc[10][4];
#pragma unroll
    for (int f = 0; f < 10; f++)
#pragma unroll
        for (int q = 0; q < 4; q++) acc[f][q] = 0.0f;

#define G1_BUFS(base) (base), (base) + 64 * SA * 2, (base) + 128 * SA * 2, (base) + 288 * SA * 2

    g1_load(sb,            m0, kbase,       tid); CP_COMMIT();
    g1_load(sb + BUF1,     m0, kbase + 64,  tid); CP_COMMIT();
    g1_load(sb + 2 * BUF1, m0, kbase + 128, tid); CP_COMMIT();

    CP_WAIT(2); __syncthreads();
    compute_chunk(G1_BUFS(sb), aRowByte, bRowByte0, acc);
    __syncthreads();
    g1_load(sb, m0, kbase + 192, tid); CP_COMMIT();

    CP_WAIT(2); __syncthreads();
    compute_chunk(G1_BUFS(sb + BUF1), aRowByte, bRowByte0, acc);

    CP_WAIT(1); __syncthreads();
    compute_chunk(G1_BUFS(sb + 2 * BUF1), aRowByte, bRowByte0, acc);

    CP_WAIT(0); __syncthreads();
    compute_chunk(G1_BUFS(sb), aRowByte, bRowByte0, acc);

    float* base = g_Spart + (size_t)ks * (B_ * NUU);
    const int r0 = m0 + wm * 16 + lg;
#pragma unroll
    for (int f = 0; f < 10; f++) {
        const int nu = wn * 80 + f * 8 + lt * 2;
        *reinterpret_cast<float2*>(base + (size_t)r0 * NUU + nu)       = make_float2(acc[f][0], acc[f][1]);
        *reinterpret_cast<float2*>(base + (size_t)(r0 + 8) * NUU + nu) = make_float2(acc[f][2], acc[f][3]);
    }
}

// ---------------------------------------------------------------------------
// GEMM2 + fused b-update partials (R11-proven):
//   G[k,nu] = sum_{b in half} Xt[k][b] Vt[nu][b];
//   bp[i*2+bsplit][j][n] = sum_u Wkn[k][nu]*G[k][nu]   (k = i*IC + j)
// grid 144 (= kt 0..71 x bsplit), 512 threads.
// ---------------------------------------------------------------------------
#define BUF2 (576 * SA * 2)          // 82944 B
#define G2_SMEM (2 * BUF2)           // 165888

__device__ __forceinline__ void g2_load(uint32_t sb, int k0, int col, int tid) {
#pragma unroll
    for (int t = 0; t < 2; t++) {
        int idx = tid + t * 512;
        int r = idx >> 3, q = idx & 7;
        uint32_t d = sb + (uint32_t)(r * SA + q * 8) * 2;
        size_t g = (size_t)(k0 + r) * B_ + col + q * 8;
        cpasync(d, g_xth + g);
        cpasync(d + 128 * SA * 2, g_xtl + g);
    }
#pragma unroll
    for (int t = 0; t < 3; t++) {
        int idx = tid + t * 512;
        if (idx < 1280) {
            int r = idx >> 3, q = idx & 7;
            uint32_t d = sb + 256 * SA * 2 + (uint32_t)(r * SA + q * 8) * 2;
            size_t g = (size_t)r * B_ + col + q * 8;
            cpasync(d, g_Vth + g);
            cpasync(d + 160 * SA * 2, g_Vtl + g);
        }
    }
}

__global__ void __launch_bounds__(512) k_hmma2() {
    extern __shared__ char sm[];
    const int ksp = blockIdx.x & 1;
    const int k0 = (blockIdx.x >> 1) * 128;
    const int col0 = ksp * 128;
    const int tid = threadIdx.x, warp = tid >> 5, lane = tid & 31;
    const int wm = warp >> 1, wn = warp & 1;
    const int lg = lane >> 2, lt = lane & 3;
    const uint32_t sb = smem_to_u32(sm);

    const int aRowByte = ((wm * 16 + (lane & 15)) * SA + (lane >> 4) * 8) * 2;
    const int bRowByte0 = ((wn * 80 + (lane & 15)) * SA + (lane >> 4) * 8) * 2;

    float acc[10][4];
#pragma unroll
    for (int f = 0; f < 10; f++)
#pragma unroll
        for (int q = 0; q < 4; q++) acc[f][q] = 0.0f;

    g2_load(sb,        k0, col0,      tid); CP_COMMIT();
    g2_load(sb + BUF2, k0, col0 + 64, tid); CP_COMMIT();

#define G2_BUFS(base) (base), (base) + 128 * SA * 2, (base) + 256 * SA * 2, (base) + 416 * SA * 2

    CP_WAIT(1); __syncthreads();
    compute_chunk(G2_BUFS(sb), aRowByte, bRowByte0, acc);

    CP_WAIT(0); __syncthreads();
    compute_chunk(G2_BUFS(sb + BUF2), aRowByte, bRowByte0, acc);

    // fused epilogue: contract with Wkn, quad-reduce over lt, emit bp partials.
    const int i_idx = k0 / IC;                 // 1152 = 9*128: tiles don't cross i
    const int j0 = k0 % IC;
    float* bp = g_bp + ((size_t)(i_idx * 2 + ksp) * IC + j0) * NU_;
    const int rbase = wm * 16 + lg;
#pragma unroll
    for (int rh = 0; rh < 2; rh++) {
        const int row = rbase + rh * 8;
        const float* wrow = g_Wkn + (size_t)(k0 + row) * NUU;
#pragma unroll
        for (int q = 0; q < 5; q++) {
            const int f0 = 2 * q;
            const int nu0 = wn * 80 + f0 * 8 + lt * 2;
            float2 w0 = *reinterpret_cast<const float2*>(wrow + nu0);
            float2 w1 = *reinterpret_cast<const float2*>(wrow + nu0 + 8);
            float s = acc[f0][rh * 2] * w0.x + acc[f0][rh * 2 + 1] * w0.y
                    + acc[f0 + 1][rh * 2] * w1.x + acc[f0 + 1][rh * 2 + 1] * w1.y;
            s += __shfl_xor_sync(0xffffffffu, s, 1);
            s += __shfl_xor_sync(0xffffffffu, s, 2);
            if (lt == 0) bp[(size_t)row * NU_ + wn * 5 + q] = s;
        }
    }
}

// ---------------------------------------------------------------------------
// k_squash: reduce 36 splits (12 groups x 3, float4 loads), squash.
// grid 256, 480 threads. (R11-proven)
// ---------------------------------------------------------------------------
__global__ void __launch_bounds__(480) k_squash(float* __restrict__ out, int final_iter) {
    const int b = blockIdx.x;
    const int tid = threadIdx.x;          // 0..479
    const int g = tid / 40, q4 = tid - (tid / 40) * 40;

    __shared__ float partial[12][NUU];
    __shared__ float sq[NUU];
    __shared__ float mag[US];

    float4 s4 = make_float4(0.f, 0.f, 0.f, 0.f);
#pragma unroll
    for (int m = 0; m < 3; m++) {
        const float4 v = *reinterpret_cast<const float4*>(
            g_Spart + (size_t)(g * 3 + m) * (B_ * NUU) + b * NUU + q4 * 4);
        s4.x += v.x; s4.y += v.y; s4.z += v.z; s4.w += v.w;
    }
    *reinterpret_cast<float4*>(&partial[g][q4 * 4]) = s4;
    __syncthreads();

    if (tid < NUU) {
        float s = 0.0f;
#pragma unroll
        for (int gg = 0; gg < 12; gg++) s += partial[gg][tid];
        sq[tid] = s * s;
        partial[0][tid] = s;
    }
    __syncthreads();
    if (tid < US) {
        float m = 0.0f;
#pragma unroll
        for (int n = 0; n < NU_; n++) m += sq[n * US + tid];
        mag[tid] = m;
    }
    __syncthreads();
    if (tid < NUU) {
        float s = partial[0][tid];
        float m = mag[tid & 15];
        float v = s * (m / ((1.0f + m) * sqrtf(m)));
        if (final_iter) {
            out[b * NUU + tid] = v;
        } else {
            __nv_bfloat16 h = __float2bfloat16_rn(v);
            __nv_bfloat16 l = __float2bfloat16_rn(v - __bfloat162float(h));
            g_Vth[tid * B_ + b] = h;
            g_Vtl[tid * B_ + b] = l;
        }
    }
}

// ---------------------------------------------------------------------------
// k_bred: logits[j,n] += (1/B) * sum_{p<16} bp[p][j][n]. grid 45x256
// ---------------------------------------------------------------------------
__global__ void k_bred() {
    int gid = blockIdx.x * 256 + threadIdx.x;
    if (gid >= IC * NU_) return;
    float s = 0.0f;
#pragma unroll
    for (int p = 0; p < 16; p++)
        s += g_bp[(size_t)p * (IC * NU_) + gid];
    g_logits[gid] += s * (1.0f / (float)B_);
}

// ---------------------------------------------------------------------------
extern "C" void kernel_launch(void* const* d_in, const int* in_sizes, int n_in,
                              void* d_out, int out_size) {
    const float* x = (const float*)d_in[0];   // [256, 8, 1152]
    const float* W = (const float*)d_in[1];   // [1152, 10, 16, 8]
    float* out = (float*)d_out;

    cudaFuncSetAttribute(k_hmma1, cudaFuncAttributeMaxDynamicSharedMemorySize, G1_SMEM);
    cudaFuncSetAttribute(k_hmma2, cudaFuncAttributeMaxDynamicSharedMemorySize, G2_SMEM);

    k_prex<<<dim3(KTOT / 64, B_ / 64), 256>>>(x);
    k_pre_w<<<IC / 8, 256>>>(W);              // also emits iter-0 scaled W split

    // iter 0 (c uniform, folded into k_pre_w)
    k_hmma1<<<4 * KSPLIT, 256, G1_SMEM>>>();
    k_squash<<<B_, 480>>>(nullptr, 0);
    k_hmma2<<<144, 512, G2_SMEM>>>();
    k_bred<<<45, 256>>>();
    k_softscale<<<NUU, 256>>>();
    // iter 1
    k_hmma1<<<4 * KSPLIT, 256, G1_SMEM>>>();
    k_squash<<<B_, 480>>>(nullptr, 0);
    k_hmma2<<<144, 512, G2_SMEM>>>();
    k_bred<<<45, 256>>>();
    k_softscale<<<NUU, 256>>>();
    // iter 2 (final)
    k_hmma1<<<4 * KSPLIT, 256, G1_SMEM>>>();
    k_squash<<<B_, 480>>>(out, 1);
}